// round 1
// baseline (speedup 1.0000x reference)
#include <cuda_runtime.h>
#include <cuda_bf16.h>
#include <math.h>

// ---------------------------------------------------------------------------
// BCEDecorrelatedLoss: bce_mean, disco (distance correlation), tot = bce + 0.1*disco
//
// Inputs (metadata order): outputs[N] f32, labels[N] f32, event[N] f32, weights[N] f32
// Output: 3 floats.
//
// Math (raw weights v, sw = sum v; normedweight w = v*n/sw):
//   ra_i  = sum_j |x_i-x_j| v_j
//   rb_i  = sum_j |e_i-e_j| v_j
//   rab_i = sum_j |x_i-x_j||e_i-e_j| v_j
//   Ra = sum v_i ra_i, Rb = sum v_i rb_i, Rab = sum v_i rab_i
//   P  = sum v_i ra_i rb_i, Qa = sum v_i ra_i^2, Qb = sum v_i rb_i^2
//   Vx = sum v x, Vx2 = sum v x^2, Ve = sum v e, Ve2 = sum v e^2
//   num  = Rab/sw^2 - 2P/sw^3 + Ra*Rb/sw^4
//   dena = 2*Vx2/sw - 2*Vx^2/sw^2 - 2*Qa/sw^3 + Ra^2/sw^4
//   denb = 2*Ve2/sw - 2*Ve^2/sw^2 - 2*Qb/sw^3 + Rb^2/sw^4
//   disco = num / sqrt(dena*denb)
// ---------------------------------------------------------------------------

#define BLK      256
#define IPT      4            // i's per thread -> 1024 i's per block
#define ITILE    (BLK*IPT)
#define JCH      128          // j's per block (one smem tile)
#define MAXN     8192
#define MAXSPLIT (MAXN/JCH)   // 64
#define RBLOCKS  32

__device__ float  g_pA [MAXSPLIT][MAXN];
__device__ float  g_pB [MAXSPLIT][MAXN];
__device__ float  g_pAB[MAXSPLIT][MAXN];
__device__ double g_part[RBLOCKS][12];

__global__ __launch_bounds__(BLK)
void pair_kernel(const float* __restrict__ x, const float* __restrict__ e,
                 const float* __restrict__ w, int n)
{
    __shared__ float sx[JCH], se[JCH], sw_[JCH];
    const int js = blockIdx.y;
    const int j0 = js * JCH;
    const int t  = threadIdx.x;

    // load j tile (zero-weight padding makes out-of-range j contribute 0)
    if (t < JCH) {
        int j = j0 + t;
        bool ok = (j < n);
        sx[t]  = ok ? x[j] : 0.0f;
        se[t]  = ok ? e[j] : 0.0f;
        sw_[t] = ok ? w[j] : 0.0f;
    }
    __syncthreads();

    const int ibase = blockIdx.x * ITILE + t;
    float xi[IPT], ei[IPT];
    float accA[IPT], accB[IPT], accAB[IPT];
#pragma unroll
    for (int p = 0; p < IPT; p++) {
        int i = ibase + p * BLK;
        bool ok = (i < n);
        xi[p] = ok ? x[i] : 0.0f;
        ei[p] = ok ? e[i] : 0.0f;
        accA[p] = 0.0f; accB[p] = 0.0f; accAB[p] = 0.0f;
    }

#pragma unroll 8
    for (int k = 0; k < JCH; k++) {
        const float xj = sx[k], ej = se[k], wj = sw_[k];
#pragma unroll
        for (int p = 0; p < IPT; p++) {
            float adx = fabsf(xi[p] - xj);          // FADD + |.| modifier downstream
            float ade = fabsf(ei[p] - ej);
            float awj = adx * wj;                   // FMUL
            accA[p]  += awj;                        // FADD
            accB[p]   = fmaf(ade, wj, accB[p]);     // FFMA
            accAB[p]  = fmaf(awj, ade, accAB[p]);   // FFMA
        }
    }

#pragma unroll
    for (int p = 0; p < IPT; p++) {
        int i = ibase + p * BLK;
        if (i < n) {
            g_pA [js][i] = accA[p];
            g_pB [js][i] = accB[p];
            g_pAB[js][i] = accAB[p];
        }
    }
}

__global__ __launch_bounds__(256)
void reduce1_kernel(const float* __restrict__ x, const float* __restrict__ y,
                    const float* __restrict__ e, const float* __restrict__ w,
                    int n, int jsplit)
{
    __shared__ double sm[12][8];   // 8 warps per 256-thread block
    const int tid = threadIdx.x;
    const int gid = blockIdx.x * blockDim.x + tid;
    const int stride = gridDim.x * blockDim.x;

    double s[12];
#pragma unroll
    for (int k = 0; k < 12; k++) s[k] = 0.0;

    for (int i = gid; i < n; i += stride) {
        double ra = 0.0, rb = 0.0, rab = 0.0;
        for (int js = 0; js < jsplit; js++) {
            ra  += (double)g_pA [js][i];
            rb  += (double)g_pB [js][i];
            rab += (double)g_pAB[js][i];
        }
        double vi = (double)w[i];
        double xi = (double)x[i];
        double ei = (double)e[i];
        double yi = (double)y[i];

        s[0]  += vi;                 // sw
        s[1]  += vi * ra;            // Ra
        s[2]  += vi * rb;            // Rb
        s[3]  += vi * rab;           // Rab
        s[4]  += vi * ra * rb;       // P
        s[5]  += vi * ra * ra;       // Qa
        s[6]  += vi * rb * rb;       // Qb
        s[7]  += vi * xi;            // Vx
        s[8]  += vi * xi * xi;       // Vx2
        s[9]  += vi * ei;            // Ve
        s[10] += vi * ei * ei;       // Ve2
        // stable softplus: max(o,0) + log1p(exp(-|o|))
        double sp = fmax(xi, 0.0) + log1p(exp(-fabs(xi)));
        s[11] += (sp - xi * yi) * vi; // Sbce
    }

    // warp-shuffle reduce each of 12 sums
#pragma unroll
    for (int k = 0; k < 12; k++) {
        double v = s[k];
        for (int o = 16; o > 0; o >>= 1)
            v += __shfl_down_sync(0xffffffffu, v, o);
        if ((tid & 31) == 0) sm[k][tid >> 5] = v;
    }
    __syncthreads();
    if (tid < 12) {
        double v = 0.0;
#pragma unroll
        for (int wi = 0; wi < 8; wi++) v += sm[tid][wi];
        g_part[blockIdx.x][tid] = v;
    }
}

__global__ void reduce2_kernel(float* __restrict__ out, int n)
{
    const int tid = threadIdx.x;
    __shared__ double tot[12];
    if (tid < 12) {
        double v = 0.0;
        for (int p = 0; p < RBLOCKS; p++) v += g_part[p][tid];
        tot[tid] = v;
    }
    __syncthreads();
    if (tid == 0) {
        double sw  = tot[0];
        double Ra  = tot[1],  Rb  = tot[2],  Rab = tot[3];
        double P   = tot[4],  Qa  = tot[5],  Qb  = tot[6];
        double Vx  = tot[7],  Vx2 = tot[8];
        double Ve  = tot[9],  Ve2 = tot[10];
        double Sbce = tot[11];

        double isw  = 1.0 / sw;
        double isw2 = isw * isw;
        double isw3 = isw2 * isw;
        double isw4 = isw2 * isw2;

        double num  = Rab * isw2 - 2.0 * P * isw3 + Ra * Rb * isw4;
        double dena = 2.0 * Vx2 * isw - 2.0 * Vx * Vx * isw2
                    - 2.0 * Qa * isw3 + Ra * Ra * isw4;
        double denb = 2.0 * Ve2 * isw - 2.0 * Ve * Ve * isw2
                    - 2.0 * Qb * isw3 + Rb * Rb * isw4;

        double disco = num / sqrt(dena * denb);
        double bce   = Sbce / (double)n;

        out[0] = (float)bce;
        out[1] = (float)disco;
        out[2] = (float)(bce + 0.1 * disco);
    }
}

extern "C" void kernel_launch(void* const* d_in, const int* in_sizes, int n_in,
                              void* d_out, int out_size)
{
    const float* x = (const float*)d_in[0];   // outputs (logits)
    const float* y = (const float*)d_in[1];   // labels
    const float* e = (const float*)d_in[2];   // event
    const float* w = (const float*)d_in[3];   // weights
    float* out = (float*)d_out;
    const int n = in_sizes[0];

    int itiles = (n + ITILE - 1) / ITILE;     // 8 for n=8192
    int jsplit = (n + JCH - 1) / JCH;         // 64 for n=8192
    if (jsplit > MAXSPLIT) jsplit = MAXSPLIT; // n is 8192 per problem spec

    dim3 grid(itiles, jsplit);
    pair_kernel<<<grid, BLK>>>(x, e, w, n);
    reduce1_kernel<<<RBLOCKS, 256>>>(x, y, e, w, n, jsplit);
    reduce2_kernel<<<1, 32>>>(out, n);
}

// round 2
// speedup vs baseline: 1.6368x; 1.6368x over previous
#include <cuda_runtime.h>
#include <cuda_bf16.h>
#include <math.h>

// ---------------------------------------------------------------------------
// BCEDecorrelatedLoss: bce_mean, disco (distance correlation), tot = bce + 0.1*disco
//
// Inputs (metadata order): outputs[N] f32, labels[N] f32, event[N] f32, weights[N] f32
// Output: 3 floats.
//
// Math (raw weights v, sw = sum v):
//   ra_i  = sum_j |x_i-x_j| v_j
//   rb_i  = sum_j |e_i-e_j| v_j
//   rab_i = sum_j |x_i-x_j||e_i-e_j| v_j
//   Ra = sum v_i ra_i, Rb = sum v_i rb_i, Rab = sum v_i rab_i
//   P  = sum v_i ra_i rb_i, Qa = sum v_i ra_i^2, Qb = sum v_i rb_i^2
//   Vx = sum v x, Vx2 = sum v x^2, Ve = sum v e, Ve2 = sum v e^2
//   num  = Rab/sw^2 - 2P/sw^3 + Ra*Rb/sw^4
//   dena = 2*Vx2/sw - 2*Vx^2/sw^2 - 2*Qa/sw^3 + Ra^2/sw^4
//   denb = 2*Ve2/sw - 2*Ve^2/sw^2 - 2*Qb/sw^3 + Rb^2/sw^4
//   disco = num / sqrt(dena*denb)
// ---------------------------------------------------------------------------

#define BLK      256
#define IPT      4            // i's per thread -> 1024 i's per block
#define ITILE    (BLK*IPT)
#define JCH      128          // j's per block (one smem tile)
#define MAXN     8192
#define MAXSPLIT (MAXN/JCH)   // 64
#define RBLOCKS  32

__device__ float  g_pA [MAXSPLIT][MAXN];
__device__ float  g_pB [MAXSPLIT][MAXN];
__device__ float  g_pAB[MAXSPLIT][MAXN];
__device__ double g_part[RBLOCKS][12];

__global__ __launch_bounds__(BLK)
void pair_kernel(const float* __restrict__ x, const float* __restrict__ e,
                 const float* __restrict__ w, int n)
{
    __shared__ float sx[JCH], se[JCH], sw_[JCH];
    const int js = blockIdx.y;
    const int j0 = js * JCH;
    const int t  = threadIdx.x;

    // load j tile (zero-weight padding makes out-of-range j contribute 0)
    if (t < JCH) {
        int j = j0 + t;
        bool ok = (j < n);
        sx[t]  = ok ? x[j] : 0.0f;
        se[t]  = ok ? e[j] : 0.0f;
        sw_[t] = ok ? w[j] : 0.0f;
    }
    __syncthreads();

    const int ibase = blockIdx.x * ITILE + t;
    float xi[IPT], ei[IPT];
    float accA[IPT], accB[IPT], accAB[IPT];
#pragma unroll
    for (int p = 0; p < IPT; p++) {
        int i = ibase + p * BLK;
        bool ok = (i < n);
        xi[p] = ok ? x[i] : 0.0f;
        ei[p] = ok ? e[i] : 0.0f;
        accA[p] = 0.0f; accB[p] = 0.0f; accAB[p] = 0.0f;
    }

#pragma unroll 8
    for (int k = 0; k < JCH; k++) {
        const float xj = sx[k], ej = se[k], wj = sw_[k];
#pragma unroll
        for (int p = 0; p < IPT; p++) {
            float adx = fabsf(xi[p] - xj);          // FADD, |.| folded downstream
            float ade = fabsf(ei[p] - ej);
            float awj = adx * wj;                   // FMUL
            accA[p]  += awj;                        // FADD
            accB[p]   = fmaf(ade, wj, accB[p]);     // FFMA
            accAB[p]  = fmaf(awj, ade, accAB[p]);   // FFMA
        }
    }

#pragma unroll
    for (int p = 0; p < IPT; p++) {
        int i = ibase + p * BLK;
        if (i < n) {
            g_pA [js][i] = accA[p];
            g_pB [js][i] = accB[p];
            g_pAB[js][i] = accAB[p];
        }
    }
}

// Per-element math in fp32 (MUFU-based expf/log1pf); only the 12 global
// scalar accumulations are fp64 (12 DADD per element + shuffle reduce).
__global__ __launch_bounds__(256)
void reduce1_kernel(const float* __restrict__ x, const float* __restrict__ y,
                    const float* __restrict__ e, const float* __restrict__ w,
                    int n, int jsplit)
{
    __shared__ double sm[12][8];   // 8 warps per 256-thread block
    const int tid = threadIdx.x;
    const int gid = blockIdx.x * blockDim.x + tid;
    const int stride = gridDim.x * blockDim.x;

    double s[12];
#pragma unroll
    for (int k = 0; k < 12; k++) s[k] = 0.0;

    for (int i = gid; i < n; i += stride) {
        // gather partial rows in fp32, 4 parallel accumulators for MLP
        float ra0 = 0.f, ra1 = 0.f, rb0 = 0.f, rb1 = 0.f, rab0 = 0.f, rab1 = 0.f;
        int js = 0;
#pragma unroll 4
        for (; js + 1 < jsplit; js += 2) {
            ra0  += g_pA [js][i];   ra1  += g_pA [js + 1][i];
            rb0  += g_pB [js][i];   rb1  += g_pB [js + 1][i];
            rab0 += g_pAB[js][i];   rab1 += g_pAB[js + 1][i];
        }
        for (; js < jsplit; js++) {
            ra0 += g_pA[js][i]; rb0 += g_pB[js][i]; rab0 += g_pAB[js][i];
        }
        float ra  = ra0 + ra1;
        float rb  = rb0 + rb1;
        float rab = rab0 + rab1;

        float vi = w[i];
        float xi = x[i];
        float ei = e[i];
        float yi = y[i];

        // stable softplus in fp32: max(o,0) + log1p(exp(-|o|))
        float sp  = fmaxf(xi, 0.0f) + log1pf(expf(-fabsf(xi)));
        float bce = (sp - xi * yi) * vi;

        s[0]  += (double)vi;                  // sw
        s[1]  += (double)(vi * ra);           // Ra
        s[2]  += (double)(vi * rb);           // Rb
        s[3]  += (double)(vi * rab);          // Rab
        s[4]  += (double)(vi * ra * rb);      // P
        s[5]  += (double)(vi * ra * ra);      // Qa
        s[6]  += (double)(vi * rb * rb);      // Qb
        s[7]  += (double)(vi * xi);           // Vx
        s[8]  += (double)(vi * xi * xi);      // Vx2
        s[9]  += (double)(vi * ei);           // Ve
        s[10] += (double)(vi * ei * ei);      // Ve2
        s[11] += (double)bce;                 // Sbce
    }

    // warp-shuffle reduce each of 12 sums (fp64, small count)
#pragma unroll
    for (int k = 0; k < 12; k++) {
        double v = s[k];
        for (int o = 16; o > 0; o >>= 1)
            v += __shfl_down_sync(0xffffffffu, v, o);
        if ((tid & 31) == 0) sm[k][tid >> 5] = v;
    }
    __syncthreads();
    if (tid < 12) {
        double v = 0.0;
#pragma unroll
        for (int wi = 0; wi < 8; wi++) v += sm[tid][wi];
        g_part[blockIdx.x][tid] = v;
    }
}

__global__ void reduce2_kernel(float* __restrict__ out, int n)
{
    const int tid = threadIdx.x;
    __shared__ double tot[12];
    if (tid < 12) {
        double v = 0.0;
        for (int p = 0; p < RBLOCKS; p++) v += g_part[p][tid];
        tot[tid] = v;
    }
    __syncthreads();
    if (tid == 0) {
        double sw  = tot[0];
        double Ra  = tot[1],  Rb  = tot[2],  Rab = tot[3];
        double P   = tot[4],  Qa  = tot[5],  Qb  = tot[6];
        double Vx  = tot[7],  Vx2 = tot[8];
        double Ve  = tot[9],  Ve2 = tot[10];
        double Sbce = tot[11];

        double isw  = 1.0 / sw;
        double isw2 = isw * isw;
        double isw3 = isw2 * isw;
        double isw4 = isw2 * isw2;

        double num  = Rab * isw2 - 2.0 * P * isw3 + Ra * Rb * isw4;
        double dena = 2.0 * Vx2 * isw - 2.0 * Vx * Vx * isw2
                    - 2.0 * Qa * isw3 + Ra * Ra * isw4;
        double denb = 2.0 * Ve2 * isw - 2.0 * Ve * Ve * isw2
                    - 2.0 * Qb * isw3 + Rb * Rb * isw4;

        double disco = num / sqrt(dena * denb);
        double bce   = Sbce / (double)n;

        out[0] = (float)bce;
        out[1] = (float)disco;
        out[2] = (float)(bce + 0.1 * disco);
    }
}

extern "C" void kernel_launch(void* const* d_in, const int* in_sizes, int n_in,
                              void* d_out, int out_size)
{
    const float* x = (const float*)d_in[0];   // outputs (logits)
    const float* y = (const float*)d_in[1];   // labels
    const float* e = (const float*)d_in[2];   // event
    const float* w = (const float*)d_in[3];   // weights
    float* out = (float*)d_out;
    const int n = in_sizes[0];

    int itiles = (n + ITILE - 1) / ITILE;     // 8 for n=8192
    int jsplit = (n + JCH - 1) / JCH;         // 64 for n=8192
    if (jsplit > MAXSPLIT) jsplit = MAXSPLIT; // n is 8192 per problem spec

    dim3 grid(itiles, jsplit);
    pair_kernel<<<grid, BLK>>>(x, e, w, n);
    reduce1_kernel<<<RBLOCKS, 256>>>(x, y, e, w, n, jsplit);
    reduce2_kernel<<<1, 32>>>(out, n);
}